// round 14
// baseline (speedup 1.0000x reference)
#include <cuda_runtime.h>
#include <cuda_bf16.h>

#define EPS 1e-5f

// Scratch (device globals: allocation-free)
__device__ float g_a[256 * 32];                  // a = x@W1 + b1
__device__ float g_s[256];                       // row sums of a
__device__ float g_q[256];                       // row sums of a^2
__device__ unsigned long long g_U2[128 * 1024];  // (U[2p][col],U[2p+1][col]) pairs, col=e*32+o
__device__ float g_c[32];                        // c[o] = sum_k gamma[k]*W2[k,o]
__device__ float g_t[32];                        // t[o] = sum_k beta[k]*W2[k,o] + b2[o]

// ---- f32x2 packed helpers (Blackwell) ----
#define FMA_F32X2(acc, a, b) \
    asm("fma.rn.f32x2 %0, %1, %2, %3;" : "=l"(acc) : "l"(a), "l"(b), "l"(acc))
#define PACK2(out, lo, hi) \
    asm("mov.b64 %0, {%1, %2};" : "=l"(out) : "f"(lo), "f"(hi))
#define DUP2(out, v) \
    asm("mov.b64 %0, {%1, %1};" : "=l"(out) : "f"(v))
#define UNPACK2(lo, hi, in) \
    asm("mov.b64 {%0, %1}, %2;" : "=f"(lo), "=f"(hi) : "l"(in))

// ---------------------------------------------------------------------------
// kA (R12-proven): blocks 0..127: it = bx>>2 (8-row i-tile), ct = bx&3.
//   a = x@W1+b1 (publish a/s/q on ct==0); per-thread g[d] (coalesced);
//   U via f32x2 over packed row-pairs -> stored as u64 PAIRS to g_U2.
// block 128: c[o], t[o].
// ---------------------------------------------------------------------------
__global__ __launch_bounds__(256) void kA(const float* __restrict__ x,
                                          const float* __restrict__ W1,
                                          const float* __restrict__ b1,
                                          const float* __restrict__ gamma,
                                          const float* __restrict__ beta,
                                          const float* __restrict__ W2,
                                          const float* __restrict__ b2) {
    int bx = blockIdx.x;
    int tid = threadIdx.x;

    if (bx == 128) {
        __shared__ float rc[8][32], rt[8][32];
        int o = tid & 31, grp = tid >> 5;
        float pc = 0.f, pt = 0.f;
        int k0i = grp * 128;
#pragma unroll 8
        for (int k = k0i; k < k0i + 128; k++) {
            float w = W2[k * 32 + o];
            pc += gamma[k] * w;
            pt += beta[k] * w;
        }
        rc[grp][o] = pc;
        rt[grp][o] = pt;
        __syncthreads();
        if (tid < 32) {
            float cc = 0.f, tt = b2[o];
#pragma unroll
            for (int g = 0; g < 8; g++) { cc += rc[g][o]; tt += rt[g][o]; }
            g_c[o] = cc;
            g_t[o] = tt;
        }
        return;
    }

    int it = bx >> 2, ct = bx & 3;
    int i0 = it * 8;

    __shared__ __align__(16) float xs[8 * 256];               // 8 KB
    __shared__ float red[8][8][32];                           // 8 KB
    __shared__ __align__(16) unsigned long long as2[4][32];   // packed row pairs

    {
        const float4* xp = (const float4*)(x + i0 * 256);
        float4* sp = (float4*)xs;
        sp[tid]       = xp[tid];
        sp[tid + 256] = xp[tid + 256];
    }
    __syncthreads();

    int h = tid & 31, grp = tid >> 5;
    {
        float acc[8];
#pragma unroll
        for (int r = 0; r < 8; r++) acc[r] = 0.f;
#pragma unroll
        for (int cc = 0; cc < 8; cc++) {
            int c = grp * 32 + cc * 4;
            float w0 = W1[(c + 0) * 32 + h];
            float w1 = W1[(c + 1) * 32 + h];
            float w2 = W1[(c + 2) * 32 + h];
            float w3 = W1[(c + 3) * 32 + h];
#pragma unroll
            for (int r = 0; r < 8; r++) {
                float4 xv = *(const float4*)&xs[r * 256 + c];
                acc[r] += xv.x * w0 + xv.y * w1 + xv.z * w2 + xv.w * w3;
            }
        }
#pragma unroll
        for (int r = 0; r < 8; r++) red[grp][r][h] = acc[r];
    }
    __syncthreads();

    {
        int r = tid >> 5;
        float a = b1[h];
#pragma unroll
        for (int g = 0; g < 8; g++) a += red[g][r][h];
        if (ct == 0) g_a[(i0 + r) * 32 + h] = a;
        xs[r * 32 + h] = a;   // temp reuse
        float s = a, q = a * a;
#pragma unroll
        for (int off = 16; off; off >>= 1) {
            s += __shfl_down_sync(0xffffffffu, s, off);
            q += __shfl_down_sync(0xffffffffu, q, off);
        }
        if (ct == 0 && h == 0) { g_s[i0 + r] = s; g_q[i0 + r] = q; }
    }
    __syncthreads();
    if (tid < 128) {
        int r2 = tid >> 5, dd = tid & 31;
        unsigned long long v;
        PACK2(v, xs[(2 * r2) * 32 + dd], xs[(2 * r2 + 1) * 32 + dd]);
        as2[r2][dd] = v;
    }
    __syncthreads();

    {
        int col = ct * 256 + tid;
        int e = col >> 5, o = col & 31;
        float g[32];
#pragma unroll
        for (int d = 0; d < 32; d++)
            g[d] = gamma[d * 32 + e] * W2[(d * 32 + e) * 32 + o];

        unsigned long long acc2[4] = {0ull, 0ull, 0ull, 0ull};
#pragma unroll
        for (int d = 0; d < 32; d++) {
            unsigned long long gd;
            DUP2(gd, g[d]);
#pragma unroll
            for (int r2 = 0; r2 < 4; r2++)
                FMA_F32X2(acc2[r2], as2[r2][d], gd);
        }
        // store i-row PAIRS directly (ipair index = it*4 + r2)
#pragma unroll
        for (int r2 = 0; r2 < 4; r2++)
            g_U2[(size_t)(it * 4 + r2) * 1024 + col] = acc2[r2];
    }
}

// ---------------------------------------------------------------------------
// k3: out[i,j,o] = P_ij*(sum_e U[i,e,o]*a[j,e]) + (t[o] - Q_ij*c[o])
// Grid (8 j-chunks of 32, 64 i-tiles of 4), 256 thr = 32 o x 8 jslot.
// U i-pairs staged [p][o*34+e] (conflict-free ulonglong2 LDS); a pre-dup'd in
// smem -> ZERO dup/pack in main loop; acc[2 ipair][4 j] = 8 chains/thread.
// ---------------------------------------------------------------------------
__global__ __launch_bounds__(256, 3) void k3(float* __restrict__ out) {
    __shared__ __align__(16) unsigned long long Us2[2][32 * 34];  // 17 KB
    __shared__ __align__(16) unsigned long long adup[32][32];     // 8 KB
    __shared__ __align__(8) float2 pq[4][32];                     // 1 KB

    int tid = threadIdx.x;
    int j0 = blockIdx.x * 32, i0 = blockIdx.y * 4;
    int gip0 = blockIdx.y * 2;

    // stage U pairs: gmem [gip][e*32+o] -> smem [p][o*34+e]
#pragma unroll
    for (int k = 0; k < 8; k++) {
        int f = tid + k * 256;                 // 2048 u64
        int p = f >> 10, col = f & 1023;
        int o = col & 31, e = col >> 5;
        Us2[p][o * 34 + e] = g_U2[(size_t)(gip0 + p) * 1024 + col];
    }
    // pre-dup a: adup[j][e] = (a[j0+j][e], a[j0+j][e])
    {
        int jj = tid >> 3, e0 = (tid & 7) * 4;
        float4 av = *(const float4*)&g_a[(j0 + jj) * 32 + e0];
        unsigned long long d0, d1, d2, d3;
        DUP2(d0, av.x); DUP2(d1, av.y); DUP2(d2, av.z); DUP2(d3, av.w);
        adup[jj][e0 + 0] = d0; adup[jj][e0 + 1] = d1;
        adup[jj][e0 + 2] = d2; adup[jj][e0 + 3] = d3;
    }
    // PQ table per (il, j)
    if (tid < 128) {
        int il = tid >> 5, j = tid & 31;
        const float inv = 1.0f / 1024.0f;
        float si = g_s[i0 + il] * inv, qi = g_q[i0 + il] * inv;
        float sj = g_s[j0 + j], qj = g_q[j0 + j];
        float mu = si * sj;
        float var = qi * qj - mu * mu;
        float r = rsqrtf(var + EPS);
        pq[il][j] = make_float2(r, r * mu);
    }
    __syncthreads();

    int o = tid & 31, jslot = tid >> 5;

    unsigned long long acc[2][4];
#pragma unroll
    for (int p = 0; p < 2; p++)
#pragma unroll
        for (int jj = 0; jj < 4; jj++) acc[p][jj] = 0ull;

#pragma unroll
    for (int ec = 0; ec < 8; ec++) {
        // u pairs: 4 e x 2 ipairs, batched LDS.128 (conflict-free, lane=o)
        ulonglong2 u0a = *(const ulonglong2*)&Us2[0][o * 34 + ec * 4];
        ulonglong2 u0b = *(const ulonglong2*)&Us2[0][o * 34 + ec * 4 + 2];
        ulonglong2 u1a = *(const ulonglong2*)&Us2[1][o * 34 + ec * 4];
        ulonglong2 u1b = *(const ulonglong2*)&Us2[1][o * 34 + ec * 4 + 2];
        unsigned long long u[2][4] = {{u0a.x, u0a.y, u0b.x, u0b.y},
                                      {u1a.x, u1a.y, u1b.x, u1b.y}};
#pragma unroll
        for (int jj = 0; jj < 4; jj++) {
            const ulonglong2* bp =
                (const ulonglong2*)&adup[jslot * 4 + jj][ec * 4];
            ulonglong2 b01 = bp[0], b23 = bp[1];   // broadcast LDS.128
            FMA_F32X2(acc[0][jj], u[0][0], b01.x);
            FMA_F32X2(acc[1][jj], u[1][0], b01.x);
            FMA_F32X2(acc[0][jj], u[0][1], b01.y);
            FMA_F32X2(acc[1][jj], u[1][1], b01.y);
            FMA_F32X2(acc[0][jj], u[0][2], b23.x);
            FMA_F32X2(acc[1][jj], u[1][2], b23.x);
            FMA_F32X2(acc[0][jj], u[0][3], b23.y);
            FMA_F32X2(acc[1][jj], u[1][3], b23.y);
        }
    }

    float co = g_c[o], to = g_t[o];
#pragma unroll
    for (int p = 0; p < 2; p++) {
#pragma unroll
        for (int jj = 0; jj < 4; jj++) {
            int j = jslot * 4 + jj;
            float t0, t1;
            UNPACK2(t0, t1, acc[p][jj]);            // rows 2p, 2p+1
            float2 v0 = pq[2 * p][j];
            float2 v1 = pq[2 * p + 1][j];
            out[((size_t)(i0 + 2 * p) * 256 + j0 + j) * 32 + o] =
                v0.x * t0 + (to - v0.y * co);
            out[((size_t)(i0 + 2 * p + 1) * 256 + j0 + j) * 32 + o] =
                v1.x * t1 + (to - v1.y * co);
        }
    }
}

extern "C" void kernel_launch(void* const* d_in, const int* in_sizes, int n_in,
                              void* d_out, int out_size) {
    const float* x     = (const float*)d_in[0];
    const float* W1    = (const float*)d_in[1];
    const float* b1    = (const float*)d_in[2];
    const float* gamma = (const float*)d_in[3];
    const float* beta  = (const float*)d_in[4];
    const float* W2    = (const float*)d_in[5];
    const float* b2    = (const float*)d_in[6];
    float* out = (float*)d_out;

    kA<<<129, 256>>>(x, W1, b1, gamma, beta, W2, b2);
    k3<<<dim3(8, 64), 256>>>(out);
}

// round 16
// speedup vs baseline: 1.0387x; 1.0387x over previous
#include <cuda_runtime.h>
#include <cuda_bf16.h>

#define EPS 1e-5f

// Scratch (device globals: allocation-free)
__device__ float g_a[256 * 32];
__device__ float g_s[256];
__device__ float g_q[256];
__device__ unsigned long long g_U2[128 * 1024];  // (U[2p][col],U[2p+1][col]), col=e*32+o
__device__ float g_c[32];
__device__ float g_t[32];

// sync objects (zero-init at load; reset by last block each run -> replay-safe)
__device__ int g_flagA[32];
__device__ int g_ctrU;
__device__ int g_flagCT;
__device__ int g_ctrEnd;

// ---- f32x2 packed helpers (Blackwell) ----
#define FMA_F32X2(acc, a, b) \
    asm("fma.rn.f32x2 %0, %1, %2, %3;" : "=l"(acc) : "l"(a), "l"(b), "l"(acc))
#define PACK2(out, lo, hi) \
    asm("mov.b64 %0, {%1, %2};" : "=l"(out) : "f"(lo), "f"(hi))
#define DUP2(out, v) \
    asm("mov.b64 %0, {%1, %1};" : "=l"(out) : "f"(v))
#define UNPACK2(lo, hi, in) \
    asm("mov.b64 {%0, %1}, %2;" : "=f"(lo), "=f"(hi) : "l"(in))

#define SMEM_BYTES 36864

__global__ __launch_bounds__(256, 2) void kfused(
    const float* __restrict__ x,  const float* __restrict__ W1,
    const float* __restrict__ b1, const float* __restrict__ gamma,
    const float* __restrict__ beta, const float* __restrict__ W2,
    const float* __restrict__ b2, float* __restrict__ out) {
    __shared__ __align__(16) unsigned char smraw[SMEM_BYTES];
    int b = blockIdx.x;
    int tid = threadIdx.x;

    // ===================== producer roles =====================
    if (b < 32) {
        // a-producer: rows i0..i0+7 (proven kA phase 1)
        float* xs = (float*)smraw;                               // 8 KB
        float (*red)[8][32] = (float (*)[8][32])(smraw + 8192);  // 8 KB
        int i0 = b * 8;
        {
            const float4* xp = (const float4*)(x + i0 * 256);
            ((float4*)xs)[tid]       = xp[tid];
            ((float4*)xs)[tid + 256] = xp[tid + 256];
        }
        __syncthreads();
        int h = tid & 31, grp = tid >> 5;
        {
            float acc[8];
#pragma unroll
            for (int r = 0; r < 8; r++) acc[r] = 0.f;
#pragma unroll
            for (int cc = 0; cc < 8; cc++) {
                int c = grp * 32 + cc * 4;
                float w0 = W1[(c + 0) * 32 + h];
                float w1 = W1[(c + 1) * 32 + h];
                float w2 = W1[(c + 2) * 32 + h];
                float w3 = W1[(c + 3) * 32 + h];
#pragma unroll
                for (int r = 0; r < 8; r++) {
                    float4 xv = *(const float4*)&xs[r * 256 + c];
                    acc[r] += xv.x * w0 + xv.y * w1 + xv.z * w2 + xv.w * w3;
                }
            }
#pragma unroll
            for (int r = 0; r < 8; r++) red[grp][r][h] = acc[r];
        }
        __syncthreads();
        {
            int r = tid >> 5;
            float a = b1[h];
#pragma unroll
            for (int g = 0; g < 8; g++) a += red[g][r][h];
            g_a[(i0 + r) * 32 + h] = a;
            float s = a, q = a * a;
#pragma unroll
            for (int off = 16; off; off >>= 1) {
                s += __shfl_down_sync(0xffffffffu, s, off);
                q += __shfl_down_sync(0xffffffffu, q, off);
            }
            if (h == 0) { g_s[i0 + r] = s; g_q[i0 + r] = q; }
        }
        __threadfence();
        __syncthreads();
        if (tid == 0) atomicExch(&g_flagA[b], 1);
    } else if (b < 160) {
        // U-producer (proven kA phase 3): itile = (b-32)>>2, ct = (b-32)&3
        unsigned long long (*as2)[32] = (unsigned long long (*)[32])smraw;
        int itile = (b - 32) >> 2, ct = (b - 32) & 3;
        int i0 = itile * 8;
        if (tid == 0) {
            while (atomicAdd(&g_flagA[itile], 0) == 0) __nanosleep(64);
        }
        __syncthreads();
        __threadfence();
        if (tid < 128) {
            int r2 = tid >> 5, dd = tid & 31;
            float a0 = g_a[(i0 + 2 * r2) * 32 + dd];
            float a1 = g_a[(i0 + 2 * r2 + 1) * 32 + dd];
            unsigned long long v;
            PACK2(v, a0, a1);
            as2[r2][dd] = v;
        }
        __syncthreads();
        {
            int col = ct * 256 + tid;
            int e = col >> 5, o = col & 31;
            float g[32];
#pragma unroll
            for (int d = 0; d < 32; d++)
                g[d] = gamma[d * 32 + e] * W2[(d * 32 + e) * 32 + o];
            unsigned long long acc2[4] = {0ull, 0ull, 0ull, 0ull};
#pragma unroll
            for (int d = 0; d < 32; d++) {
                unsigned long long gd;
                DUP2(gd, g[d]);
#pragma unroll
                for (int r2 = 0; r2 < 4; r2++)
                    FMA_F32X2(acc2[r2], as2[r2][d], gd);
            }
#pragma unroll
            for (int r2 = 0; r2 < 4; r2++)
                g_U2[(size_t)(itile * 4 + r2) * 1024 + col] = acc2[r2];
        }
        __threadfence();
        __syncthreads();
        if (tid == 0) atomicAdd(&g_ctrU, 1);
    } else if (b == 255) {
        // c/t producer
        float (*rc)[32] = (float (*)[32])smraw;
        float (*rt)[32] = (float (*)[32])(smraw + 1024);
        int o = tid & 31, grp = tid >> 5;
        float pc = 0.f, pt = 0.f;
        int k0i = grp * 128;
#pragma unroll 8
        for (int k = k0i; k < k0i + 128; k++) {
            float w = W2[k * 32 + o];
            pc += gamma[k] * w;
            pt += beta[k] * w;
        }
        rc[grp][o] = pc;
        rt[grp][o] = pt;
        __syncthreads();
        if (tid < 32) {
            float cc = 0.f, tt = b2[o];
#pragma unroll
            for (int g = 0; g < 8; g++) { cc += rc[g][o]; tt += rt[g][o]; }
            g_c[o] = cc;
            g_t[o] = tt;
        }
        __threadfence();
        __syncthreads();
        if (tid == 0) atomicExch(&g_flagCT, 1);
    }
    // blocks 160..254: straight to consumer phase

    // ===================== barrier: wait for U and c/t =====================
    if (tid == 0) {
        while (atomicAdd(&g_ctrU, 0) < 128) __nanosleep(64);
        while (atomicAdd(&g_flagCT, 0) == 0) __nanosleep(32);
    }
    __syncthreads();
    __threadfence();

    // ===================== consumer: output tile =====================
    // tile: i-tile 4 (ib = b>>2), j-chunk 64 (jc = b&3)
    int ib = b >> 2, jc = b & 3;
    int i0 = ib * 4, j0 = jc * 64;

    unsigned long long* Us2 = (unsigned long long*)smraw;                 // 2*1088*8 = 17408 B
    unsigned long long (*adup)[32] =
        (unsigned long long (*)[32])(smraw + 17408);                      // 64*32*8 = 16384 B
    float2* pq = (float2*)(smraw + 17408 + 16384);                        // 4*64*8 = 2048 B

    // stage U pairs: g_U2[gip][e*32+o] -> Us2[p*1088 + o*34 + e] (pitch 34)
#pragma unroll
    for (int k = 0; k < 8; k++) {
        int f = tid + k * 256;                 // 2048 u64
        int p = f >> 10, col = f & 1023;
        int o = col & 31, e = col >> 5;
        Us2[p * 1088 + o * 34 + e] = g_U2[(size_t)(ib * 2 + p) * 1024 + col];
    }
    // pre-dup a for 64 j rows
#pragma unroll
    for (int k = 0; k < 8; k++) {
        int idx = tid + k * 256;
        int jj = idx >> 5, e = idx & 31;
        float av = g_a[(j0 + jj) * 32 + e];
        unsigned long long v;
        DUP2(v, av);
        adup[jj][e] = v;
    }
    // PQ table: 4 il x 64 j
    {
        int il = tid >> 6, j = tid & 63;
        const float inv = 1.0f / 1024.0f;
        float si = g_s[i0 + il] * inv, qi = g_q[i0 + il] * inv;
        float mu = si * g_s[j0 + j];
        float var = qi * g_q[j0 + j] - mu * mu;
        float r = rsqrtf(var + EPS);
        pq[il * 64 + j] = make_float2(r, r * mu);
    }
    __syncthreads();

    int o = tid & 31, jslot = tid >> 5;        // 8 jslots x 8 j

    unsigned long long acc[2][8];
#pragma unroll
    for (int p = 0; p < 2; p++)
#pragma unroll
        for (int jj = 0; jj < 8; jj++) acc[p][jj] = 0ull;

#pragma unroll
    for (int ec = 0; ec < 8; ec++) {
        // u pairs: conflict-free LDS.128 (lane=o, pitch-34 u64 -> stride 4 banks/lane-quad)
        ulonglong2 u0a = *(const ulonglong2*)&Us2[0 * 1088 + o * 34 + ec * 4];
        ulonglong2 u0b = *(const ulonglong2*)&Us2[0 * 1088 + o * 34 + ec * 4 + 2];
        ulonglong2 u1a = *(const ulonglong2*)&Us2[1 * 1088 + o * 34 + ec * 4];
        ulonglong2 u1b = *(const ulonglong2*)&Us2[1 * 1088 + o * 34 + ec * 4 + 2];
        unsigned long long u[2][4] = {{u0a.x, u0a.y, u0b.x, u0b.y},
                                      {u1a.x, u1a.y, u1b.x, u1b.y}};
#pragma unroll
        for (int jj = 0; jj < 8; jj++) {
            const ulonglong2* bp =
                (const ulonglong2*)&adup[jslot * 8 + jj][ec * 4];
            ulonglong2 b01 = bp[0], b23 = bp[1];   // warp-uniform broadcast
            FMA_F32X2(acc[0][jj], u[0][0], b01.x);
            FMA_F32X2(acc[1][jj], u[1][0], b01.x);
            FMA_F32X2(acc[0][jj], u[0][1], b01.y);
            FMA_F32X2(acc[1][jj], u[1][1], b01.y);
            FMA_F32X2(acc[0][jj], u[0][2], b23.x);
            FMA_F32X2(acc[1][jj], u[1][2], b23.x);
            FMA_F32X2(acc[0][jj], u[0][3], b23.y);
            FMA_F32X2(acc[1][jj], u[1][3], b23.y);
        }
    }

    // epilogue
    {
        float co = g_c[o], to = g_t[o];
#pragma unroll
        for (int p = 0; p < 2; p++) {
#pragma unroll
            for (int jj = 0; jj < 8; jj++) {
                int j = jslot * 8 + jj;
                float t0, t1;
                UNPACK2(t0, t1, acc[p][jj]);       // rows i0+2p, i0+2p+1
                float2 v0 = pq[(2 * p) * 64 + j];
                float2 v1 = pq[(2 * p + 1) * 64 + j];
                out[((size_t)(i0 + 2 * p) * 256 + j0 + j) * 32 + o] =
                    v0.x * t0 + (to - v0.y * co);
                out[((size_t)(i0 + 2 * p + 1) * 256 + j0 + j) * 32 + o] =
                    v1.x * t1 + (to - v1.y * co);
            }
        }
    }

    // ===================== reset sync state for next replay =====================
    __syncthreads();
    if (tid == 0) {
        int v = atomicAdd(&g_ctrEnd, 1);
        if (v == 255) {                 // last block: everyone else is done
#pragma unroll
            for (int i = 0; i < 32; i++) g_flagA[i] = 0;
            g_ctrU = 0;
            g_flagCT = 0;
            __threadfence();
            g_ctrEnd = 0;
        }
    }
}

extern "C" void kernel_launch(void* const* d_in, const int* in_sizes, int n_in,
                              void* d_out, int out_size) {
    const float* x     = (const float*)d_in[0];
    const float* W1    = (const float*)d_in[1];
    const float* b1    = (const float*)d_in[2];
    const float* gamma = (const float*)d_in[3];
    const float* beta  = (const float*)d_in[4];
    const float* W2    = (const float*)d_in[5];
    const float* b2    = (const float*)d_in[6];
    float* out = (float*)d_out;

    kfused<<<256, 256>>>(x, W1, b1, gamma, beta, W2, b2, out);
}